// round 1
// baseline (speedup 1.0000x reference)
#include <cuda_runtime.h>
#include <math.h>

#define BSZ 4
#define TLEN 2048
#define DM 512
#define NH 8
#define HD 64
#define BT (BSZ*TLEN)

// scratch (allowed: __device__ globals, no runtime allocation)
__device__ float g_q[BT * DM];
__device__ float g_k[BT * DM];
__device__ float g_v[BT * DM];
__device__ float g_att[BT * DM];

// ---------------------------------------------------------------------------
// Projection GEMM. Handles the causal conv1d as a shifted GEMM:
//   q[b,t,n] = sum_{f,c} x[b, t-(FS-1)+f, c] * W[(f*D+c)*512 + n]   (+bias)
// For FS=1 this is a plain dense GEMM (the V projection).
// 128x128 tile, BK=8, 256 threads, 8x8 micro-tile per thread.
// ---------------------------------------------------------------------------
__global__ __launch_bounds__(256) void proj_kernel(const float* __restrict__ x,
                                                   const float* __restrict__ W,
                                                   const float* __restrict__ bias,
                                                   int which, int FS)
{
    float* outp = (which == 0) ? g_q : (which == 1 ? g_k : g_v);
    const int K = FS * DM;

    __shared__ float As[8][132];   // [k][m], pad 132 -> conflict-free stores
    __shared__ float Bs[8][128];   // [k][n]

    const int tid = threadIdx.x;
    const int tx  = tid & 15;
    const int ty  = tid >> 4;
    const int m0  = blockIdx.x * 128;
    const int n0  = blockIdx.y * 128;
    const int b   = m0 / TLEN;       // 128 | 2048 -> whole tile in one batch
    const int tb  = m0 % TLEN;

    const int a_m = tid >> 1;        // 0..127
    const int a_k = (tid & 1) * 4;   // 0 or 4
    const int b_k = tid >> 5;        // 0..7
    const int b_n = (tid & 31) * 4;  // 0..124

    float acc[8][8];
#pragma unroll
    for (int i = 0; i < 8; i++)
#pragma unroll
        for (int j = 0; j < 8; j++) acc[i][j] = 0.f;

    for (int k0 = 0; k0 < K; k0 += 8) {
        // Within a BK=8 tile the conv tap f is constant (512 % 8 == 0).
        const int f  = k0 >> 9;                 // k0 / 512
        const int c0 = (k0 & 511) + a_k;
        const int ts = tb + a_m - (FS - 1) + f; // source time (left pad -> 0)
        float4 av = make_float4(0.f, 0.f, 0.f, 0.f);
        if (ts >= 0)
            av = *(const float4*)&x[((size_t)(b * TLEN + ts)) * DM + c0];
        As[a_k + 0][a_m] = av.x;
        As[a_k + 1][a_m] = av.y;
        As[a_k + 2][a_m] = av.z;
        As[a_k + 3][a_m] = av.w;

        *(float4*)&Bs[b_k][b_n] =
            *(const float4*)&W[(size_t)(k0 + b_k) * DM + n0 + b_n];

        __syncthreads();
#pragma unroll
        for (int kk = 0; kk < 8; kk++) {
            float4 a0 = *(float4*)&As[kk][ty * 8];
            float4 a1 = *(float4*)&As[kk][ty * 8 + 4];
            float4 b0 = *(float4*)&Bs[kk][tx * 8];
            float4 b1 = *(float4*)&Bs[kk][tx * 8 + 4];
            float ar[8] = {a0.x, a0.y, a0.z, a0.w, a1.x, a1.y, a1.z, a1.w};
            float br[8] = {b0.x, b0.y, b0.z, b0.w, b1.x, b1.y, b1.z, b1.w};
#pragma unroll
            for (int i = 0; i < 8; i++)
#pragma unroll
                for (int j = 0; j < 8; j++) acc[i][j] += ar[i] * br[j];
        }
        __syncthreads();
    }

#pragma unroll
    for (int i = 0; i < 8; i++) {
        const size_t row = (size_t)(m0 + ty * 8 + i);
#pragma unroll
        for (int j = 0; j < 8; j++) {
            const int n = n0 + tx * 8 + j;
            outp[row * DM + n] = acc[i][j] + bias[n];
        }
    }
}

// ---------------------------------------------------------------------------
// Flash attention, fp32. One block per (query tile of 64, b*h).
// 256 threads; thread (ty,tx) owns rows ty*4+i, cols tx+16*j (interleaved
// column mapping -> conflict-free K^T and V smem reads).
// P is written back into the K buffer (K no longer needed after S).
// ---------------------------------------------------------------------------
#define ATT_SMEM_FLOATS (64*66 + 64*65 + 64*64)

extern __shared__ float sm_att[];

__global__ __launch_bounds__(256) void attn_kernel()
{
    float* Qs = sm_att;              // [64][66]
    float* Ks = Qs + 64 * 66;        // [64][65]  (reused as P)
    float* Vs = Ks + 64 * 65;        // [64][64]

    const int tid = threadIdx.x;
    const int tx  = tid & 15;
    const int ty  = tid >> 4;
    const int bh  = blockIdx.y;
    const int b   = bh >> 3;
    const int h   = bh & 7;
    const int qt  = blockIdx.x;
    const int t0  = qt * 64;

    const float* qp = g_q + (size_t)b * TLEN * DM + h * HD;
    const float* kp = g_k + (size_t)b * TLEN * DM + h * HD;
    const float* vp = g_v + (size_t)b * TLEN * DM + h * HD;

    // Q tile -> smem
#pragma unroll
    for (int it = 0; it < 4; it++) {
        int lin = (tid + it * 256) * 4;
        int m = lin >> 6;
        int d = lin & 63;
        float4 v = *(const float4*)&qp[(size_t)(t0 + m) * DM + d];
        Qs[m * 66 + d + 0] = v.x;
        Qs[m * 66 + d + 1] = v.y;
        Qs[m * 66 + d + 2] = v.z;
        Qs[m * 66 + d + 3] = v.w;
    }

    float mrow[4], lrow[4], O[4][4];
#pragma unroll
    for (int i = 0; i < 4; i++) {
        mrow[i] = -1e30f;
        lrow[i] = 0.f;
#pragma unroll
        for (int j = 0; j < 4; j++) O[i][j] = 0.f;
    }

    for (int kt = 0; kt <= qt; kt++) {
        const int kt0 = kt * 64;
        __syncthreads();   // previous iteration's P/V reads complete
#pragma unroll
        for (int it = 0; it < 4; it++) {
            int lin = (tid + it * 256) * 4;
            int m = lin >> 6;
            int d = lin & 63;
            float4 kv4 = *(const float4*)&kp[(size_t)(kt0 + m) * DM + d];
            Ks[m * 65 + d + 0] = kv4.x;
            Ks[m * 65 + d + 1] = kv4.y;
            Ks[m * 65 + d + 2] = kv4.z;
            Ks[m * 65 + d + 3] = kv4.w;
            float4 vv4 = *(const float4*)&vp[(size_t)(kt0 + m) * DM + d];
            Vs[m * 64 + d + 0] = vv4.x;
            Vs[m * 64 + d + 1] = vv4.y;
            Vs[m * 64 + d + 2] = vv4.z;
            Vs[m * 64 + d + 3] = vv4.w;
        }
        __syncthreads();

        // S = Q K^T
        float s[4][4];
#pragma unroll
        for (int i = 0; i < 4; i++)
#pragma unroll
            for (int j = 0; j < 4; j++) s[i][j] = 0.f;
#pragma unroll 8
        for (int d = 0; d < 64; d++) {
            float qv[4], kv[4];
#pragma unroll
            for (int i = 0; i < 4; i++) qv[i] = Qs[(ty * 4 + i) * 66 + d];
#pragma unroll
            for (int j = 0; j < 4; j++) kv[j] = Ks[(tx + 16 * j) * 65 + d];
#pragma unroll
            for (int i = 0; i < 4; i++)
#pragma unroll
                for (int j = 0; j < 4; j++) s[i][j] += qv[i] * kv[j];
        }

        // scale + causal mask (diagonal tile only)
        const bool diag = (kt == qt);
#pragma unroll
        for (int i = 0; i < 4; i++)
#pragma unroll
            for (int j = 0; j < 4; j++) {
                float sv = s[i][j] * 0.125f;
                if (diag && (kt0 + tx + 16 * j > t0 + ty * 4 + i)) sv = -1e30f;
                s[i][j] = sv;
            }

        // online softmax (row stats shared across the 16-lane tx group)
#pragma unroll
        for (int i = 0; i < 4; i++) {
            float v = fmaxf(fmaxf(s[i][0], s[i][1]), fmaxf(s[i][2], s[i][3]));
            for (int off = 8; off >= 1; off >>= 1)
                v = fmaxf(v, __shfl_xor_sync(0xffffffffu, v, off, 16));
            float mnew  = fmaxf(mrow[i], v);
            float alpha = __expf(mrow[i] - mnew);
            mrow[i] = mnew;
            lrow[i] *= alpha;
            float su = 0.f;
#pragma unroll
            for (int j = 0; j < 4; j++) {
                float p = __expf(s[i][j] - mnew);
                s[i][j] = p;
                su += p;
            }
            for (int off = 8; off >= 1; off >>= 1)
                su += __shfl_xor_sync(0xffffffffu, su, off, 16);
            lrow[i] += su;
#pragma unroll
            for (int j = 0; j < 4; j++) O[i][j] *= alpha;
        }

        __syncthreads();   // all K reads done -> safe to overwrite with P
#pragma unroll
        for (int i = 0; i < 4; i++)
#pragma unroll
            for (int j = 0; j < 4; j++)
                Ks[(ty * 4 + i) * 65 + tx + 16 * j] = s[i][j];
        __syncthreads();

        // O += P V
#pragma unroll 8
        for (int kv = 0; kv < 64; kv++) {
            float pv[4], vv[4];
#pragma unroll
            for (int i = 0; i < 4; i++) pv[i] = Ks[(ty * 4 + i) * 65 + kv];
#pragma unroll
            for (int j = 0; j < 4; j++) vv[j] = Vs[kv * 64 + tx + 16 * j];
#pragma unroll
            for (int i = 0; i < 4; i++)
#pragma unroll
                for (int j = 0; j < 4; j++) O[i][j] += pv[i] * vv[j];
        }
    }

#pragma unroll
    for (int i = 0; i < 4; i++) {
        float inv = 1.f / lrow[i];
        size_t row = (size_t)(b * TLEN + t0 + ty * 4 + i);
#pragma unroll
        for (int j = 0; j < 4; j++)
            g_att[row * DM + h * HD + tx + 16 * j] = O[i][j] * inv;
    }
}

// ---------------------------------------------------------------------------
// Fused MLP: out = relu(att @ W1 + b1) @ W2 + b2.  One block per 64 rows.
// ---------------------------------------------------------------------------
__global__ __launch_bounds__(256) void mlp_kernel(const float* __restrict__ W1,
                                                  const float* __restrict__ b1,
                                                  const float* __restrict__ W2,
                                                  const float* __restrict__ b2,
                                                  float* __restrict__ out)
{
    __shared__ float W2s[64 * 65];
    __shared__ float Hs[64 * 65];
    __shared__ float As[64 * 17];
    __shared__ float W1s[16 * 65];

    const int tid = threadIdx.x;
    const int tx  = tid & 15;
    const int ty  = tid >> 4;
    const int r0  = blockIdx.x * 64;

    // W2 -> smem once
#pragma unroll
    for (int it = 0; it < 4; it++) {
        int lin = (tid + it * 256) * 4;
        int m = lin >> 6, n = lin & 63;
        float4 w = *(const float4*)&W2[m * 64 + n];
        W2s[m * 65 + n + 0] = w.x;
        W2s[m * 65 + n + 1] = w.y;
        W2s[m * 65 + n + 2] = w.z;
        W2s[m * 65 + n + 3] = w.w;
    }

    float acc1[4][4];
#pragma unroll
    for (int i = 0; i < 4; i++)
#pragma unroll
        for (int j = 0; j < 4; j++) acc1[i][j] = 0.f;

    for (int ct = 0; ct < DM; ct += 16) {
        __syncthreads();
        {   // A tile 64x16
            int m = tid >> 2;
            int c = (tid & 3) * 4;
            float4 a = *(const float4*)&g_att[(size_t)(r0 + m) * DM + ct + c];
            As[m * 17 + c + 0] = a.x;
            As[m * 17 + c + 1] = a.y;
            As[m * 17 + c + 2] = a.z;
            As[m * 17 + c + 3] = a.w;
        }
        {   // W1 tile 16x64
            int c = tid >> 4;
            int n = (tid & 15) * 4;
            float4 w = *(const float4*)&W1[(size_t)(ct + c) * 64 + n];
            W1s[c * 65 + n + 0] = w.x;
            W1s[c * 65 + n + 1] = w.y;
            W1s[c * 65 + n + 2] = w.z;
            W1s[c * 65 + n + 3] = w.w;
        }
        __syncthreads();
#pragma unroll
        for (int c = 0; c < 16; c++) {
            float a[4], w[4];
#pragma unroll
            for (int i = 0; i < 4; i++) a[i] = As[(ty * 4 + i) * 17 + c];
#pragma unroll
            for (int j = 0; j < 4; j++) w[j] = W1s[c * 65 + tx + 16 * j];
#pragma unroll
            for (int i = 0; i < 4; i++)
#pragma unroll
                for (int j = 0; j < 4; j++) acc1[i][j] += a[i] * w[j];
        }
    }

    __syncthreads();
#pragma unroll
    for (int i = 0; i < 4; i++)
#pragma unroll
        for (int j = 0; j < 4; j++)
            Hs[(ty * 4 + i) * 65 + tx + 16 * j] =
                fmaxf(acc1[i][j] + b1[tx + 16 * j], 0.f);
    __syncthreads();

    float acc2[4][4];
#pragma unroll
    for (int i = 0; i < 4; i++)
#pragma unroll
        for (int j = 0; j < 4; j++) acc2[i][j] = 0.f;
#pragma unroll 8
    for (int kv = 0; kv < 64; kv++) {
        float hv[4], w[4];
#pragma unroll
        for (int i = 0; i < 4; i++) hv[i] = Hs[(ty * 4 + i) * 65 + kv];
#pragma unroll
        for (int j = 0; j < 4; j++) w[j] = W2s[kv * 65 + tx + 16 * j];
#pragma unroll
        for (int i = 0; i < 4; i++)
#pragma unroll
            for (int j = 0; j < 4; j++) acc2[i][j] += hv[i] * w[j];
    }

#pragma unroll
    for (int i = 0; i < 4; i++)
#pragma unroll
        for (int j = 0; j < 4; j++)
            out[(size_t)(r0 + ty * 4 + i) * 64 + tx + 16 * j] =
                acc2[i][j] + b2[tx + 16 * j];
}

// ---------------------------------------------------------------------------
extern "C" void kernel_launch(void* const* d_in, const int* in_sizes, int n_in,
                              void* d_out, int out_size)
{
    const float* x  = (const float*)d_in[0];
    const float* Wq = (const float*)d_in[1];
    const float* bq = (const float*)d_in[2];
    const float* Wk = (const float*)d_in[3];
    const float* bk = (const float*)d_in[4];
    const float* Wv = (const float*)d_in[5];
    const float* bv = (const float*)d_in[6];
    const float* W1 = (const float*)d_in[7];
    const float* b1 = (const float*)d_in[8];
    const float* W2 = (const float*)d_in[9];
    const float* b2 = (const float*)d_in[10];
    float* out = (float*)d_out;

    const int att_smem = ATT_SMEM_FLOATS * (int)sizeof(float);   // 49920 B
    cudaFuncSetAttribute(attn_kernel,
                         cudaFuncAttributeMaxDynamicSharedMemorySize, att_smem);

    dim3 pg(BT / 128, DM / 128);   // (64, 4)
    proj_kernel<<<pg, 256>>>(x, Wq, bq, 0, 3);
    proj_kernel<<<pg, 256>>>(x, Wk, bk, 1, 3);
    proj_kernel<<<pg, 256>>>(x, Wv, bv, 2, 1);

    attn_kernel<<<dim3(TLEN / 64, BSZ * NH), 256, att_smem>>>();

    mlp_kernel<<<BT / 64, 256>>>(W1, b1, W2, b2, out);
}

// round 3
// speedup vs baseline: 1.3669x; 1.3669x over previous
#include <cuda_runtime.h>
#include <cuda_bf16.h>
#include <cstdint>
#include <math.h>

#define BSZ 4
#define TLEN 2048
#define DM 512
#define NH 8
#define HD 64
#define BT (BSZ*TLEN)

// ---------------------------------------------------------------------------
// device scratch (no runtime allocation allowed)
// ---------------------------------------------------------------------------
__device__ float g_q[BT * DM];
__device__ float g_k[BT * DM];
__device__ float g_v[BT * DM];
__device__ float g_att[BT * DM];

__device__ __nv_bfloat16 g_xhi[BT * DM];
__device__ __nv_bfloat16 g_xlo[BT * DM];
__device__ __nv_bfloat16 g_wqhi[3 * DM * DM];   // transposed: [512][1536]
__device__ __nv_bfloat16 g_wqlo[3 * DM * DM];
__device__ __nv_bfloat16 g_wkhi[3 * DM * DM];
__device__ __nv_bfloat16 g_wklo[3 * DM * DM];
__device__ __nv_bfloat16 g_wvhi[DM * DM];       // transposed: [512][512]
__device__ __nv_bfloat16 g_wvlo[DM * DM];

extern __shared__ unsigned char dynsm[];

// ---------------------------------------------------------------------------
__device__ __forceinline__ uint32_t smem_u32(const void* p) {
    uint32_t a;
    asm("{ .reg .u64 t; cvta.to.shared.u64 t, %1; cvt.u32.u64 %0, t; }"
        : "=r"(a) : "l"(p));
    return a;
}

__device__ __forceinline__ void ldmatrix_x4(uint32_t& r0, uint32_t& r1,
                                            uint32_t& r2, uint32_t& r3,
                                            uint32_t addr) {
    asm volatile("ldmatrix.sync.aligned.m8n8.x4.shared.b16 {%0,%1,%2,%3}, [%4];"
                 : "=r"(r0), "=r"(r1), "=r"(r2), "=r"(r3) : "r"(addr));
}

__device__ __forceinline__ void mma_bf16(float* d, const uint32_t* a,
                                         uint32_t b0, uint32_t b1) {
    asm volatile(
        "mma.sync.aligned.m16n8k16.row.col.f32.bf16.bf16.f32 "
        "{%0,%1,%2,%3}, {%4,%5,%6,%7}, {%8,%9}, {%0,%1,%2,%3};"
        : "+f"(d[0]), "+f"(d[1]), "+f"(d[2]), "+f"(d[3])
        : "r"(a[0]), "r"(a[1]), "r"(a[2]), "r"(a[3]), "r"(b0), "r"(b1));
}

// ---------------------------------------------------------------------------
// Prep: split x into bf16 hi/lo
// ---------------------------------------------------------------------------
__global__ __launch_bounds__(256) void split_x_kernel(const float* __restrict__ x)
{
    int i = (blockIdx.x * 256 + threadIdx.x) * 4;
    if (i >= BT * DM) return;
    float4 a = *(const float4*)&x[i];
    float av[4] = {a.x, a.y, a.z, a.w};
#pragma unroll
    for (int j = 0; j < 4; j++) {
        __nv_bfloat16 h = __float2bfloat16(av[j]);
        g_xhi[i + j] = h;
        g_xlo[i + j] = __float2bfloat16(av[j] - __bfloat162float(h));
    }
}

// ---------------------------------------------------------------------------
// Prep: transpose W[K][512] -> Wt[512][K] and split hi/lo
// ---------------------------------------------------------------------------
__global__ __launch_bounds__(256) void tsplit_w_kernel(const float* __restrict__ W,
                                                       int which, int K)
{
    __nv_bfloat16* hiT = (which == 0) ? g_wqhi : (which == 1 ? g_wkhi : g_wvhi);
    __nv_bfloat16* loT = (which == 0) ? g_wqlo : (which == 1 ? g_wklo : g_wvlo);
    __shared__ float t[32][33];
    const int tx = threadIdx.x & 31;
    const int ty = threadIdx.x >> 5;      // 0..7
    const int k0 = blockIdx.x * 32;
    const int n0 = blockIdx.y * 32;
#pragma unroll
    for (int i = 0; i < 4; i++)
        t[ty + 8 * i][tx] = W[(size_t)(k0 + ty + 8 * i) * DM + n0 + tx];
    __syncthreads();
#pragma unroll
    for (int i = 0; i < 4; i++) {
        float a = t[tx][ty + 8 * i];
        __nv_bfloat16 h = __float2bfloat16(a);
        size_t idx = (size_t)(n0 + ty + 8 * i) * K + k0 + tx;
        hiT[idx] = h;
        loT[idx] = __float2bfloat16(a - __bfloat162float(h));
    }
}

// ---------------------------------------------------------------------------
// mma.sync bf16x3 projection GEMM.
//   out[m][n] = sum_k A[m][k] * W[k][n] + bias[n]
// A = time-shifted x (causal conv as GEMM).  W pre-transposed to [N][K].
// Block tile 128x128, K-chunk 32, 8 warps (warp tile 32x64).
// ---------------------------------------------------------------------------
#define AKP 40   // padded row length (bf16) -> 80B stride, ldmatrix conflict-free

__global__ __launch_bounds__(256) void proj_mma_kernel(const float* __restrict__ bias,
                                                       int which, int K, int shift)
{
    const __nv_bfloat16* whiT = (which == 0) ? g_wqhi : (which == 1 ? g_wkhi : g_wvhi);
    const __nv_bfloat16* wloT = (which == 0) ? g_wqlo : (which == 1 ? g_wklo : g_wvlo);
    float* outp = (which == 0) ? g_q : (which == 1 ? g_k : g_v);

    __shared__ __nv_bfloat16 Ahi[128][AKP];
    __shared__ __nv_bfloat16 Alo[128][AKP];
    __shared__ __nv_bfloat16 Bhi[128][AKP];
    __shared__ __nv_bfloat16 Blo[128][AKP];

    const int tid  = threadIdx.x;
    const int warp = tid >> 5;
    const int lane = tid & 31;
    const int m0 = blockIdx.x * 128;
    const int n0 = blockIdx.y * 128;
    const int b  = m0 / TLEN;
    const int tb = m0 % TLEN;

    const int warp_m = (warp & 3) * 32;
    const int warp_n = (warp >> 2) * 64;

    // per-lane ldmatrix source rows/cols
    const int a_row = warp_m + (lane & 15);
    const int a_col = (lane >> 4) << 3;
    const int b_row = warp_n + ((lane >> 4) << 3) + (lane & 7);
    const int b_col = ((lane >> 3) & 1) << 3;

    float acc[2][8][4];
#pragma unroll
    for (int mi = 0; mi < 2; mi++)
#pragma unroll
        for (int nf = 0; nf < 8; nf++)
#pragma unroll
            for (int c = 0; c < 4; c++) acc[mi][nf][c] = 0.f;

    for (int k0 = 0; k0 < K; k0 += 32) {
        const int f  = k0 >> 9;            // conv tap (const within 32-chunk)
        const int c0 = k0 & 511;
        __syncthreads();
#pragma unroll
        for (int it = 0; it < 2; it++) {
            int idx = tid + it * 256;      // 0..511
            int row = idx >> 2;            // 0..127
            int seg = (idx & 3) << 3;      // 0,8,16,24
            // A (shifted x)
            int ts = tb + row - shift + f;
            uint4 vh = make_uint4(0, 0, 0, 0), vl = make_uint4(0, 0, 0, 0);
            if (ts >= 0) {
                size_t g = ((size_t)(b * TLEN + ts)) * DM + c0 + seg;
                vh = *(const uint4*)&g_xhi[g];
                vl = *(const uint4*)&g_xlo[g];
            }
            *(uint4*)&Ahi[row][seg] = vh;
            *(uint4*)&Alo[row][seg] = vl;
            // B (transposed weights [N][K])
            size_t gb = (size_t)(n0 + row) * K + k0 + seg;
            *(uint4*)&Bhi[row][seg] = *(const uint4*)&whiT[gb];
            *(uint4*)&Blo[row][seg] = *(const uint4*)&wloT[gb];
        }
        __syncthreads();

#pragma unroll
        for (int ks = 0; ks < 32; ks += 16) {
            uint32_t ah[2][4], al[2][4];
#pragma unroll
            for (int mi = 0; mi < 2; mi++) {
                uint32_t adr = smem_u32(&Ahi[a_row + mi * 16][ks + a_col]);
                ldmatrix_x4(ah[mi][0], ah[mi][1], ah[mi][2], ah[mi][3], adr);
                adr = smem_u32(&Alo[a_row + mi * 16][ks + a_col]);
                ldmatrix_x4(al[mi][0], al[mi][1], al[mi][2], al[mi][3], adr);
            }
            uint32_t bh[4][4], bl[4][4];
#pragma unroll
            for (int pi = 0; pi < 4; pi++) {
                uint32_t adr = smem_u32(&Bhi[b_row + pi * 16][ks + b_col]);
                ldmatrix_x4(bh[pi][0], bh[pi][1], bh[pi][2], bh[pi][3], adr);
                adr = smem_u32(&Blo[b_row + pi * 16][ks + b_col]);
                ldmatrix_x4(bl[pi][0], bl[pi][1], bl[pi][2], bl[pi][3], adr);
            }
#pragma unroll
            for (int mi = 0; mi < 2; mi++)
#pragma unroll
                for (int nf = 0; nf < 8; nf++) {
                    const int pi = nf >> 1;
                    const int hh = (nf & 1) << 1;
                    mma_bf16(acc[mi][nf], ah[mi], bh[pi][hh], bh[pi][hh + 1]);
                    mma_bf16(acc[mi][nf], ah[mi], bl[pi][hh], bl[pi][hh + 1]);
                    mma_bf16(acc[mi][nf], al[mi], bh[pi][hh], bh[pi][hh + 1]);
                }
        }
    }

    // epilogue
#pragma unroll
    for (int mi = 0; mi < 2; mi++) {
        const int r = m0 + warp_m + mi * 16 + (lane >> 2);
#pragma unroll
        for (int nf = 0; nf < 8; nf++) {
            const int cc = n0 + warp_n + nf * 8 + (lane & 3) * 2;
            const float bx = __ldg(&bias[cc]);
            const float by = __ldg(&bias[cc + 1]);
            *(float2*)&outp[(size_t)r * DM + cc] =
                make_float2(acc[mi][nf][0] + bx, acc[mi][nf][1] + by);
            *(float2*)&outp[(size_t)(r + 8) * DM + cc] =
                make_float2(acc[mi][nf][2] + bx, acc[mi][nf][3] + by);
        }
    }
}

// ---------------------------------------------------------------------------
// Flash attention, fp32 (unchanged — known good).
// ---------------------------------------------------------------------------
#define ATT_SMEM_FLOATS (64*66 + 64*65 + 64*64)

__global__ __launch_bounds__(256) void attn_kernel()
{
    float* Qs = (float*)dynsm;       // [64][66]
    float* Ks = Qs + 64 * 66;        // [64][65]  (reused as P)
    float* Vs = Ks + 64 * 65;        // [64][64]

    const int tid = threadIdx.x;
    const int tx  = tid & 15;
    const int ty  = tid >> 4;
    const int bh  = blockIdx.y;
    const int b   = bh >> 3;
    const int h   = bh & 7;
    const int qt  = blockIdx.x;
    const int t0  = qt * 64;

    const float* qp = g_q + (size_t)b * TLEN * DM + h * HD;
    const float* kp = g_k + (size_t)b * TLEN * DM + h * HD;
    const float* vp = g_v + (size_t)b * TLEN * DM + h * HD;

#pragma unroll
    for (int it = 0; it < 4; it++) {
        int lin = (tid + it * 256) * 4;
        int m = lin >> 6;
        int d = lin & 63;
        float4 v = *(const float4*)&qp[(size_t)(t0 + m) * DM + d];
        Qs[m * 66 + d + 0] = v.x;
        Qs[m * 66 + d + 1] = v.y;
        Qs[m * 66 + d + 2] = v.z;
        Qs[m * 66 + d + 3] = v.w;
    }

    float mrow[4], lrow[4], O[4][4];
#pragma unroll
    for (int i = 0; i < 4; i++) {
        mrow[i] = -1e30f;
        lrow[i] = 0.f;
#pragma unroll
        for (int j = 0; j < 4; j++) O[i][j] = 0.f;
    }

    for (int kt = 0; kt <= qt; kt++) {
        const int kt0 = kt * 64;
        __syncthreads();
#pragma unroll
        for (int it = 0; it < 4; it++) {
            int lin = (tid + it * 256) * 4;
            int m = lin >> 6;
            int d = lin & 63;
            float4 kv4 = *(const float4*)&kp[(size_t)(kt0 + m) * DM + d];
            Ks[m * 65 + d + 0] = kv4.x;
            Ks[m * 65 + d + 1] = kv4.y;
            Ks[m * 65 + d + 2] = kv4.z;
            Ks[m * 65 + d + 3] = kv4.w;
            float4 vv4 = *(const float4*)&vp[(size_t)(kt0 + m) * DM + d];
            Vs[m * 64 + d + 0] = vv4.x;
            Vs[m * 64 + d + 1] = vv4.y;
            Vs[m * 64 + d + 2] = vv4.z;
            Vs[m * 64 + d + 3] = vv4.w;
        }
        __syncthreads();

        float s[4][4];
#pragma unroll
        for (int i = 0; i < 4; i++)
#pragma unroll
            for (int j = 0; j < 4; j++) s[i][j] = 0.f;
#pragma unroll 8
        for (int d = 0; d < 64; d++) {
            float qv[4], kv[4];
#pragma unroll
            for (int i = 0; i < 4; i++) qv[i] = Qs[(ty * 4 + i) * 66 + d];
#pragma unroll
            for (int j = 0; j < 4; j++) kv[j] = Ks[(tx + 16 * j) * 65 + d];
#pragma unroll
            for (int i = 0; i < 4; i++)
#pragma unroll
                for (int j = 0; j < 4; j++) s[i][j] += qv[i] * kv[j];
        }

        const bool diag = (kt == qt);
#pragma unroll
        for (int i = 0; i < 4; i++)
#pragma unroll
            for (int j = 0; j < 4; j++) {
                float sv = s[i][j] * 0.125f;
                if (diag && (kt0 + tx + 16 * j > t0 + ty * 4 + i)) sv = -1e30f;
                s[i][j] = sv;
            }

#pragma unroll
        for (int i = 0; i < 4; i++) {
            float v = fmaxf(fmaxf(s[i][0], s[i][1]), fmaxf(s[i][2], s[i][3]));
            for (int off = 8; off >= 1; off >>= 1)
                v = fmaxf(v, __shfl_xor_sync(0xffffffffu, v, off, 16));
            float mnew  = fmaxf(mrow[i], v);
            float alpha = __expf(mrow[i] - mnew);
            mrow[i] = mnew;
            lrow[i] *= alpha;
            float su = 0.f;
#pragma unroll
            for (int j = 0; j < 4; j++) {
                float p = __expf(s[i][j] - mnew);
                s[i][j] = p;
                su += p;
            }
            for (int off = 8; off >= 1; off >>= 1)
                su += __shfl_xor_sync(0xffffffffu, su, off, 16);
            lrow[i] += su;
#pragma unroll
            for (int j = 0; j < 4; j++) O[i][j] *= alpha;
        }

        __syncthreads();
#pragma unroll
        for (int i = 0; i < 4; i++)
#pragma unroll
            for (int j = 0; j < 4; j++)
                Ks[(ty * 4 + i) * 65 + tx + 16 * j] = s[i][j];
        __syncthreads();

#pragma unroll 8
        for (int kv = 0; kv < 64; kv++) {
            float pv[4], vv[4];
#pragma unroll
            for (int i = 0; i < 4; i++) pv[i] = Ks[(ty * 4 + i) * 65 + kv];
#pragma unroll
            for (int j = 0; j < 4; j++) vv[j] = Vs[kv * 64 + tx + 16 * j];
#pragma unroll
            for (int i = 0; i < 4; i++)
#pragma unroll
                for (int j = 0; j < 4; j++) O[i][j] += pv[i] * vv[j];
        }
    }

#pragma unroll
    for (int i = 0; i < 4; i++) {
        float inv = 1.f / lrow[i];
        size_t row = (size_t)(b * TLEN + t0 + ty * 4 + i);
#pragma unroll
        for (int j = 0; j < 4; j++)
            g_att[row * DM + h * HD + tx + 16 * j] = O[i][j] * inv;
    }
}

// ---------------------------------------------------------------------------
// Fused MLP (unchanged).
// ---------------------------------------------------------------------------
__global__ __launch_bounds__(256) void mlp_kernel(const float* __restrict__ W1,
                                                  const float* __restrict__ b1,
                                                  const float* __restrict__ W2,
                                                  const float* __restrict__ b2,
                                                  float* __restrict__ out)
{
    __shared__ float W2s[64 * 65];
    __shared__ float Hs[64 * 65];
    __shared__ float As[64 * 17];
    __shared__ float W1s[16 * 65];

    const int tid = threadIdx.x;
    const int tx  = tid & 15;
    const int ty  = tid >> 4;
    const int r0  = blockIdx.x * 64;

#pragma unroll
    for (int it = 0; it < 4; it++) {
        int lin = (tid + it * 256) * 4;
        int m = lin >> 6, n = lin & 63;
        float4 w = *(const float4*)&W2[m * 64 + n];
        W2s[m * 65 + n + 0] = w.x;
        W2s[m * 65 + n + 1] = w.y;
        W2s[m * 65 + n + 2] = w.z;
        W2s[m * 65 + n + 3] = w.w;
    }

    float acc1[4][4];
#pragma unroll
    for (int i = 0; i < 4; i++)
#pragma unroll
        for (int j = 0; j < 4; j++) acc1[i][j] = 0.f;

    for (int ct = 0; ct < DM; ct += 16) {
        __syncthreads();
        {
            int m = tid >> 2;
            int c = (tid & 3) * 4;
            float4 a = *(const float4*)&g_att[(size_t)(r0 + m) * DM + ct + c];
            As[m * 17 + c + 0] = a.x;
            As[m * 17 + c + 1] = a.y;
            As[m * 17 + c + 2] = a.z;
            As[m * 17 + c + 3] = a.w;
        }
        {
            int c = tid >> 4;
            int n = (tid & 15) * 4;
            float4 w = *(const float4*)&W1[(size_t)(ct + c) * 64 + n];
            W1s[c * 65 + n + 0] = w.x;
            W1s[c * 65 + n + 1] = w.y;
            W1s[c * 65 + n + 2] = w.z;
            W1s[c * 65 + n + 3] = w.w;
        }
        __syncthreads();
#pragma unroll
        for (int c = 0; c < 16; c++) {
            float a[4], w[4];
#pragma unroll
            for (int i = 0; i < 4; i++) a[i] = As[(ty * 4 + i) * 17 + c];
#pragma unroll
            for (int j = 0; j < 4; j++) w[j] = W1s[c * 65 + tx + 16 * j];
#pragma unroll
            for (int i = 0; i < 4; i++)
#pragma unroll
                for (int j = 0; j < 4; j++) acc1[i][j] += a[i] * w[j];
        }
    }

    __syncthreads();
#pragma unroll
    for (int i = 0; i < 4; i++)
#pragma unroll
        for (int j = 0; j < 4; j++)
            Hs[(ty * 4 + i) * 65 + tx + 16 * j] =
                fmaxf(acc1[i][j] + b1[tx + 16 * j], 0.f);
    __syncthreads();

    float acc2[4][4];
#pragma unroll
    for (int i = 0; i < 4; i++)
#pragma unroll
        for (int j = 0; j < 4; j++) acc2[i][j] = 0.f;
#pragma unroll 8
    for (int kv = 0; kv < 64; kv++) {
        float hv[4], w[4];
#pragma unroll
        for (int i = 0; i < 4; i++) hv[i] = Hs[(ty * 4 + i) * 65 + kv];
#pragma unroll
        for (int j = 0; j < 4; j++) w[j] = W2s[kv * 65 + tx + 16 * j];
#pragma unroll
        for (int i = 0; i < 4; i++)
#pragma unroll
            for (int j = 0; j < 4; j++) acc2[i][j] += hv[i] * w[j];
    }

#pragma unroll
    for (int i = 0; i < 4; i++)
#pragma unroll
        for (int j = 0; j < 4; j++)
            out[(size_t)(r0 + ty * 4 + i) * 64 + tx + 16 * j] =
                acc2[i][j] + b2[tx + 16 * j];
}

// ---------------------------------------------------------------------------
extern "C" void kernel_launch(void* const* d_in, const int* in_sizes, int n_in,
                              void* d_out, int out_size)
{
    const float* x  = (const float*)d_in[0];
    const float* Wq = (const float*)d_in[1];
    const float* bq = (const float*)d_in[2];
    const float* Wk = (const float*)d_in[3];
    const float* bk = (const float*)d_in[4];
    const float* Wv = (const float*)d_in[5];
    const float* bv = (const float*)d_in[6];
    const float* W1 = (const float*)d_in[7];
    const float* b1 = (const float*)d_in[8];
    const float* W2 = (const float*)d_in[9];
    const float* b2 = (const float*)d_in[10];
    float* out = (float*)d_out;

    // prep: bf16 hi/lo splits + W transposes
    split_x_kernel<<<(BT * DM / 4 + 255) / 256, 256>>>(x);
    tsplit_w_kernel<<<dim3(3 * DM / 32, DM / 32), 256>>>(Wq, 0, 3 * DM);
    tsplit_w_kernel<<<dim3(3 * DM / 32, DM / 32), 256>>>(Wk, 1, 3 * DM);
    tsplit_w_kernel<<<dim3(DM / 32, DM / 32), 256>>>(Wv, 2, DM);

    // mma.sync bf16x3 projections
    dim3 pg(BT / 128, DM / 128);   // (64, 4)
    proj_mma_kernel<<<pg, 256>>>(bq, 0, 3 * DM, 2);
    proj_mma_kernel<<<pg, 256>>>(bk, 1, 3 * DM, 2);
    proj_mma_kernel<<<pg, 256>>>(bv, 2, DM, 0);

    // attention (fp32 flash)
    const int att_smem = ATT_SMEM_FLOATS * (int)sizeof(float);   // 49920 B
    cudaFuncSetAttribute(attn_kernel,
                         cudaFuncAttributeMaxDynamicSharedMemorySize, att_smem);
    attn_kernel<<<dim3(TLEN / 64, BSZ * NH), 256, att_smem>>>();

    mlp_kernel<<<BT / 64, 256>>>(W1, b1, W2, b2, out);
}

// round 4
// speedup vs baseline: 2.2074x; 1.6148x over previous
#include <cuda_runtime.h>
#include <cuda_bf16.h>
#include <cstdint>
#include <math.h>

#define BSZ 4
#define TLEN 2048
#define DM 512
#define NH 8
#define HD 64
#define BT (BSZ*TLEN)

// ---------------------------------------------------------------------------
// device scratch (no runtime allocation allowed)
// ---------------------------------------------------------------------------
__device__ float g_att[BT * DM];

__device__ __nv_bfloat16 g_xhi[BT * DM];
__device__ __nv_bfloat16 g_xlo[BT * DM];
__device__ __nv_bfloat16 g_wqhi[3 * DM * DM];   // transposed: [512][1536]
__device__ __nv_bfloat16 g_wqlo[3 * DM * DM];
__device__ __nv_bfloat16 g_wkhi[3 * DM * DM];
__device__ __nv_bfloat16 g_wklo[3 * DM * DM];
__device__ __nv_bfloat16 g_wvhi[DM * DM];       // transposed: [512][512]
__device__ __nv_bfloat16 g_wvlo[DM * DM];

// projection outputs, bf16 hi/lo (q pre-scaled by 1/sqrt(DK))
__device__ __nv_bfloat16 g_qhi[BT * DM];
__device__ __nv_bfloat16 g_qlo[BT * DM];
__device__ __nv_bfloat16 g_khi[BT * DM];
__device__ __nv_bfloat16 g_klo[BT * DM];
__device__ __nv_bfloat16 g_vhi[BT * DM];
__device__ __nv_bfloat16 g_vlo[BT * DM];

extern __shared__ unsigned char dynsm[];

// ---------------------------------------------------------------------------
__device__ __forceinline__ uint32_t smem_u32(const void* p) {
    uint32_t a;
    asm("{ .reg .u64 t; cvta.to.shared.u64 t, %1; cvt.u32.u64 %0, t; }"
        : "=r"(a) : "l"(p));
    return a;
}

__device__ __forceinline__ void ldmatrix_x4(uint32_t& r0, uint32_t& r1,
                                            uint32_t& r2, uint32_t& r3,
                                            uint32_t addr) {
    asm volatile("ldmatrix.sync.aligned.m8n8.x4.shared.b16 {%0,%1,%2,%3}, [%4];"
                 : "=r"(r0), "=r"(r1), "=r"(r2), "=r"(r3) : "r"(addr));
}

__device__ __forceinline__ void ldmatrix_x4_trans(uint32_t& r0, uint32_t& r1,
                                                  uint32_t& r2, uint32_t& r3,
                                                  uint32_t addr) {
    asm volatile("ldmatrix.sync.aligned.m8n8.x4.trans.shared.b16 {%0,%1,%2,%3}, [%4];"
                 : "=r"(r0), "=r"(r1), "=r"(r2), "=r"(r3) : "r"(addr));
}

__device__ __forceinline__ void mma_bf16(float* d, const uint32_t* a,
                                         uint32_t b0, uint32_t b1) {
    asm volatile(
        "mma.sync.aligned.m16n8k16.row.col.f32.bf16.bf16.f32 "
        "{%0,%1,%2,%3}, {%4,%5,%6,%7}, {%8,%9}, {%0,%1,%2,%3};"
        : "+f"(d[0]), "+f"(d[1]), "+f"(d[2]), "+f"(d[3])
        : "r"(a[0]), "r"(a[1]), "r"(a[2]), "r"(a[3]), "r"(b0), "r"(b1));
}

// ---------------------------------------------------------------------------
// Prep: split x into bf16 hi/lo
// ---------------------------------------------------------------------------
__global__ __launch_bounds__(256) void split_x_kernel(const float* __restrict__ x)
{
    int i = (blockIdx.x * 256 + threadIdx.x) * 4;
    if (i >= BT * DM) return;
    float4 a = *(const float4*)&x[i];
    float av[4] = {a.x, a.y, a.z, a.w};
#pragma unroll
    for (int j = 0; j < 4; j++) {
        __nv_bfloat16 h = __float2bfloat16(av[j]);
        g_xhi[i + j] = h;
        g_xlo[i + j] = __float2bfloat16(av[j] - __bfloat162float(h));
    }
}

// ---------------------------------------------------------------------------
// Prep: transpose W[K][512] -> Wt[512][K] and split hi/lo
// ---------------------------------------------------------------------------
__global__ __launch_bounds__(256) void tsplit_w_kernel(const float* __restrict__ W,
                                                       int which, int K)
{
    __nv_bfloat16* hiT = (which == 0) ? g_wqhi : (which == 1 ? g_wkhi : g_wvhi);
    __nv_bfloat16* loT = (which == 0) ? g_wqlo : (which == 1 ? g_wklo : g_wvlo);
    __shared__ float t[32][33];
    const int tx = threadIdx.x & 31;
    const int ty = threadIdx.x >> 5;      // 0..7
    const int k0 = blockIdx.x * 32;
    const int n0 = blockIdx.y * 32;
#pragma unroll
    for (int i = 0; i < 4; i++)
        t[ty + 8 * i][tx] = W[(size_t)(k0 + ty + 8 * i) * DM + n0 + tx];
    __syncthreads();
#pragma unroll
    for (int i = 0; i < 4; i++) {
        float a = t[tx][ty + 8 * i];
        __nv_bfloat16 h = __float2bfloat16(a);
        size_t idx = (size_t)(n0 + ty + 8 * i) * K + k0 + tx;
        hiT[idx] = h;
        loT[idx] = __float2bfloat16(a - __bfloat162float(h));
    }
}

// ---------------------------------------------------------------------------
// mma.sync bf16x3 projection GEMM -> bf16 hi/lo outputs.
// ---------------------------------------------------------------------------
#define AKP 40   // padded row length (bf16) -> 80B stride, ldmatrix conflict-free

__global__ __launch_bounds__(256) void proj_mma_kernel(const float* __restrict__ bias,
                                                       int which, int K, int shift)
{
    const __nv_bfloat16* whiT = (which == 0) ? g_wqhi : (which == 1 ? g_wkhi : g_wvhi);
    const __nv_bfloat16* wloT = (which == 0) ? g_wqlo : (which == 1 ? g_wklo : g_wvlo);
    __nv_bfloat16* ohi = (which == 0) ? g_qhi : (which == 1 ? g_khi : g_vhi);
    __nv_bfloat16* olo = (which == 0) ? g_qlo : (which == 1 ? g_klo : g_vlo);
    const float sc = (which == 0) ? 0.125f : 1.0f;

    __shared__ __nv_bfloat16 Ahi[128][AKP];
    __shared__ __nv_bfloat16 Alo[128][AKP];
    __shared__ __nv_bfloat16 Bhi[128][AKP];
    __shared__ __nv_bfloat16 Blo[128][AKP];

    const int tid  = threadIdx.x;
    const int warp = tid >> 5;
    const int lane = tid & 31;
    const int m0 = blockIdx.x * 128;
    const int n0 = blockIdx.y * 128;
    const int b  = m0 / TLEN;
    const int tb = m0 % TLEN;

    const int warp_m = (warp & 3) * 32;
    const int warp_n = (warp >> 2) * 64;

    const int a_row = warp_m + (lane & 15);
    const int a_col = (lane >> 4) << 3;
    const int b_row = warp_n + ((lane >> 4) << 3) + (lane & 7);
    const int b_col = ((lane >> 3) & 1) << 3;

    float acc[2][8][4];
#pragma unroll
    for (int mi = 0; mi < 2; mi++)
#pragma unroll
        for (int nf = 0; nf < 8; nf++)
#pragma unroll
            for (int c = 0; c < 4; c++) acc[mi][nf][c] = 0.f;

    for (int k0 = 0; k0 < K; k0 += 32) {
        const int f  = k0 >> 9;
        const int c0 = k0 & 511;
        __syncthreads();
#pragma unroll
        for (int it = 0; it < 2; it++) {
            int idx = tid + it * 256;
            int row = idx >> 2;
            int seg = (idx & 3) << 3;
            int ts = tb + row - shift + f;
            uint4 vh = make_uint4(0, 0, 0, 0), vl = make_uint4(0, 0, 0, 0);
            if (ts >= 0) {
                size_t g = ((size_t)(b * TLEN + ts)) * DM + c0 + seg;
                vh = *(const uint4*)&g_xhi[g];
                vl = *(const uint4*)&g_xlo[g];
            }
            *(uint4*)&Ahi[row][seg] = vh;
            *(uint4*)&Alo[row][seg] = vl;
            size_t gb = (size_t)(n0 + row) * K + k0 + seg;
            *(uint4*)&Bhi[row][seg] = *(const uint4*)&whiT[gb];
            *(uint4*)&Blo[row][seg] = *(const uint4*)&wloT[gb];
        }
        __syncthreads();

#pragma unroll
        for (int ks = 0; ks < 32; ks += 16) {
            uint32_t ah[2][4], al[2][4];
#pragma unroll
            for (int mi = 0; mi < 2; mi++) {
                uint32_t adr = smem_u32(&Ahi[a_row + mi * 16][ks + a_col]);
                ldmatrix_x4(ah[mi][0], ah[mi][1], ah[mi][2], ah[mi][3], adr);
                adr = smem_u32(&Alo[a_row + mi * 16][ks + a_col]);
                ldmatrix_x4(al[mi][0], al[mi][1], al[mi][2], al[mi][3], adr);
            }
            uint32_t bh[4][4], bl[4][4];
#pragma unroll
            for (int pi = 0; pi < 4; pi++) {
                uint32_t adr = smem_u32(&Bhi[b_row + pi * 16][ks + b_col]);
                ldmatrix_x4(bh[pi][0], bh[pi][1], bh[pi][2], bh[pi][3], adr);
                adr = smem_u32(&Blo[b_row + pi * 16][ks + b_col]);
                ldmatrix_x4(bl[pi][0], bl[pi][1], bl[pi][2], bl[pi][3], adr);
            }
#pragma unroll
            for (int mi = 0; mi < 2; mi++)
#pragma unroll
                for (int nf = 0; nf < 8; nf++) {
                    const int pi = nf >> 1;
                    const int hh = (nf & 1) << 1;
                    mma_bf16(acc[mi][nf], ah[mi], bh[pi][hh], bh[pi][hh + 1]);
                    mma_bf16(acc[mi][nf], ah[mi], bl[pi][hh], bl[pi][hh + 1]);
                    mma_bf16(acc[mi][nf], al[mi], bh[pi][hh], bh[pi][hh + 1]);
                }
        }
    }

    // epilogue: write bf16 hi/lo (q scaled by 0.125)
#pragma unroll
    for (int mi = 0; mi < 2; mi++) {
        const int r = m0 + warp_m + mi * 16 + (lane >> 2);
#pragma unroll
        for (int nf = 0; nf < 8; nf++) {
            const int cc = n0 + warp_n + nf * 8 + (lane & 3) * 2;
            const float bx = __ldg(&bias[cc]);
            const float by = __ldg(&bias[cc + 1]);
            float v0 = (acc[mi][nf][0] + bx) * sc;
            float v1 = (acc[mi][nf][1] + by) * sc;
            float v2 = (acc[mi][nf][2] + bx) * sc;
            float v3 = (acc[mi][nf][3] + by) * sc;
            __nv_bfloat16 h0 = __float2bfloat16(v0);
            __nv_bfloat16 h1 = __float2bfloat16(v1);
            __nv_bfloat16 h2 = __float2bfloat16(v2);
            __nv_bfloat16 h3 = __float2bfloat16(v3);
            *(__nv_bfloat162*)&ohi[(size_t)r * DM + cc] = __halves2bfloat162(h0, h1);
            *(__nv_bfloat162*)&ohi[(size_t)(r + 8) * DM + cc] = __halves2bfloat162(h2, h3);
            __nv_bfloat16 l0 = __float2bfloat16(v0 - __bfloat162float(h0));
            __nv_bfloat16 l1 = __float2bfloat16(v1 - __bfloat162float(h1));
            __nv_bfloat16 l2 = __float2bfloat16(v2 - __bfloat162float(h2));
            __nv_bfloat16 l3 = __float2bfloat16(v3 - __bfloat162float(h3));
            *(__nv_bfloat162*)&olo[(size_t)r * DM + cc] = __halves2bfloat162(l0, l1);
            *(__nv_bfloat162*)&olo[(size_t)(r + 8) * DM + cc] = __halves2bfloat162(l2, l3);
        }
    }
}

// ---------------------------------------------------------------------------
// Flash attention with mma.sync bf16x3.
// Block: 128 q-rows x (b,h). 8 warps x 16 q-rows. K tiles of 64 keys.
// P stays in registers (C-frag -> A-frag identity), V via ldmatrix.trans.
// smem: single 36864B buffer (Q staging aliases K/V tiles).
// ---------------------------------------------------------------------------
#define ATT_DYNSM 36864

__global__ __launch_bounds__(256) void attn_mma_kernel()
{
    __nv_bfloat16* S = (__nv_bfloat16*)dynsm;
    __nv_bfloat16* Khi = S;              // [64][72]
    __nv_bfloat16* Klo = S + 4608;
    __nv_bfloat16* Vhi = S + 9216;
    __nv_bfloat16* Vlo = S + 13824;
    __nv_bfloat16* Qhi_s = S;            // staging alias [128][72]
    __nv_bfloat16* Qlo_s = S + 9216;

    const int tid  = threadIdx.x;
    const int warp = tid >> 5;
    const int lane = tid & 31;
    const int qt = (int)gridDim.x - 1 - (int)blockIdx.x;   // heavy tiles first
    const int t0 = qt * 128;
    const int bh = blockIdx.y;
    const int b  = bh >> 3;
    const int h  = bh & 7;
    const int wrow0 = warp * 16;

    // ---- stage Q tile and build register fragments (hi/lo) ----
    {
        const size_t base = (size_t)(b * TLEN + t0) * DM + h * HD;
#pragma unroll
        for (int it = 0; it < 4; it++) {
            int idx = tid + it * 256;        // 0..1023
            int row = idx >> 3;
            int seg = (idx & 7) * 8;
            *(uint4*)&Qhi_s[row * 72 + seg] = *(const uint4*)&g_qhi[base + (size_t)row * DM + seg];
            *(uint4*)&Qlo_s[row * 72 + seg] = *(const uint4*)&g_qlo[base + (size_t)row * DM + seg];
        }
    }
    __syncthreads();

    uint32_t qh[4][4], ql[4][4];
    {
        const int a_row = wrow0 + (lane & 15);
        const int a_col = (lane >> 4) << 3;
#pragma unroll
        for (int ks = 0; ks < 4; ks++) {
            uint32_t adr = smem_u32(&Qhi_s[a_row * 72 + ks * 16 + a_col]);
            ldmatrix_x4(qh[ks][0], qh[ks][1], qh[ks][2], qh[ks][3], adr);
            adr = smem_u32(&Qlo_s[a_row * 72 + ks * 16 + a_col]);
            ldmatrix_x4(ql[ks][0], ql[ks][1], ql[ks][2], ql[ks][3], adr);
        }
    }

    float o[8][4];
#pragma unroll
    for (int nf = 0; nf < 8; nf++)
#pragma unroll
        for (int c = 0; c < 4; c++) o[nf][c] = 0.f;
    float mrow[2] = {-1e30f, -1e30f};
    float lrow[2] = {0.f, 0.f};

    const int brow = ((lane >> 4) << 3) + (lane & 7);
    const int bcol = ((lane >> 3) & 1) << 3;
    const int vrow = ((lane >> 3) & 1) * 8 + (lane & 7);
    const int vcol = (lane >> 4) << 3;

    const int nkt = 2 * qt + 2;
    const size_t kvstride = (size_t)DM;
    for (int kt = 0; kt < nkt; kt++) {
        const int kt0 = kt * 64;
        __syncthreads();   // previous iteration's smem reads done
        {
            const size_t base = (size_t)(b * TLEN + kt0) * DM + h * HD;
#pragma unroll
            for (int it = 0; it < 2; it++) {
                int idx = tid + it * 256;     // 0..511
                int row = idx >> 3;
                int seg = (idx & 7) * 8;
                size_t g = base + (size_t)row * kvstride + seg;
                int so = row * 72 + seg;
                *(uint4*)&Khi[so] = *(const uint4*)&g_khi[g];
                *(uint4*)&Klo[so] = *(const uint4*)&g_klo[g];
                *(uint4*)&Vhi[so] = *(const uint4*)&g_vhi[g];
                *(uint4*)&Vlo[so] = *(const uint4*)&g_vlo[g];
            }
        }
        __syncthreads();

        if (kt0 <= t0 + wrow0 + 15) {    // warp has unmasked keys in this tile
            // ---- S = Q K^T (bf16x3) ----
            float s[8][4];
#pragma unroll
            for (int nf = 0; nf < 8; nf++)
#pragma unroll
                for (int c = 0; c < 4; c++) s[nf][c] = 0.f;
#pragma unroll
            for (int ks = 0; ks < 4; ks++) {
#pragma unroll
                for (int pi = 0; pi < 4; pi++) {
                    uint32_t kh4[4], kl4[4];
                    uint32_t adr = smem_u32(&Khi[(pi * 16 + brow) * 72 + ks * 16 + bcol]);
                    ldmatrix_x4(kh4[0], kh4[1], kh4[2], kh4[3], adr);
                    adr = smem_u32(&Klo[(pi * 16 + brow) * 72 + ks * 16 + bcol]);
                    ldmatrix_x4(kl4[0], kl4[1], kl4[2], kl4[3], adr);
                    mma_bf16(s[pi * 2],     qh[ks], kh4[0], kh4[1]);
                    mma_bf16(s[pi * 2],     qh[ks], kl4[0], kl4[1]);
                    mma_bf16(s[pi * 2],     ql[ks], kh4[0], kh4[1]);
                    mma_bf16(s[pi * 2 + 1], qh[ks], kh4[2], kh4[3]);
                    mma_bf16(s[pi * 2 + 1], qh[ks], kl4[2], kl4[3]);
                    mma_bf16(s[pi * 2 + 1], ql[ks], kh4[2], kh4[3]);
                }
            }

            // ---- causal mask (only near the diagonal) ----
            if (kt0 + 63 > t0 + wrow0) {
                const int r0g = t0 + wrow0 + (lane >> 2);
#pragma unroll
                for (int nf = 0; nf < 8; nf++)
#pragma unroll
                    for (int c = 0; c < 4; c++) {
                        int col = kt0 + nf * 8 + (lane & 3) * 2 + (c & 1);
                        int row = r0g + ((c >> 1) * 8);
                        if (col > row) s[nf][c] = -1e30f;
                    }
            }

            // ---- online softmax (rows r0g via c0/c1, r0g+8 via c2/c3) ----
#pragma unroll
            for (int half = 0; half < 2; half++) {
                const int c0 = half * 2;
                float mx = -1e30f;
#pragma unroll
                for (int nf = 0; nf < 8; nf++)
                    mx = fmaxf(mx, fmaxf(s[nf][c0], s[nf][c0 + 1]));
                mx = fmaxf(mx, __shfl_xor_sync(0xffffffffu, mx, 1));
                mx = fmaxf(mx, __shfl_xor_sync(0xffffffffu, mx, 2));
                float mnew  = fmaxf(mrow[half], mx);
                float alpha = __expf(mrow[half] - mnew);
                mrow[half] = mnew;
                float sum = 0.f;
#pragma unroll
                for (int nf = 0; nf < 8; nf++) {
                    float p0 = __expf(s[nf][c0] - mnew);
                    float p1 = __expf(s[nf][c0 + 1] - mnew);
                    s[nf][c0] = p0;
                    s[nf][c0 + 1] = p1;
                    sum += p0 + p1;
                }
                sum += __shfl_xor_sync(0xffffffffu, sum, 1);
                sum += __shfl_xor_sync(0xffffffffu, sum, 2);
                lrow[half] = lrow[half] * alpha + sum;
#pragma unroll
                for (int nf = 0; nf < 8; nf++) {
                    o[nf][c0] *= alpha;
                    o[nf][c0 + 1] *= alpha;
                }
            }

            // ---- O += P V (P hi/lo in registers, V via ldmatrix.trans) ----
#pragma unroll
            for (int kv = 0; kv < 4; kv++) {
                uint32_t ph[4], pl[4];
                {
                    const float* pa = s[2 * kv];
                    const float* pb = s[2 * kv + 1];
                    __nv_bfloat16 ha0 = __float2bfloat16(pa[0]);
                    __nv_bfloat16 ha1 = __float2bfloat16(pa[1]);
                    __nv_bfloat16 ha2 = __float2bfloat16(pa[2]);
                    __nv_bfloat16 ha3 = __float2bfloat16(pa[3]);
                    __nv_bfloat16 hb0 = __float2bfloat16(pb[0]);
                    __nv_bfloat16 hb1 = __float2bfloat16(pb[1]);
                    __nv_bfloat16 hb2 = __float2bfloat16(pb[2]);
                    __nv_bfloat16 hb3 = __float2bfloat16(pb[3]);
                    __nv_bfloat162 t;
                    t = __halves2bfloat162(ha0, ha1); ph[0] = *(uint32_t*)&t;
                    t = __halves2bfloat162(ha2, ha3); ph[1] = *(uint32_t*)&t;
                    t = __halves2bfloat162(hb0, hb1); ph[2] = *(uint32_t*)&t;
                    t = __halves2bfloat162(hb2, hb3); ph[3] = *(uint32_t*)&t;
                    __nv_bfloat16 la0 = __float2bfloat16(pa[0] - __bfloat162float(ha0));
                    __nv_bfloat16 la1 = __float2bfloat16(pa[1] - __bfloat162float(ha1));
                    __nv_bfloat16 la2 = __float2bfloat16(pa[2] - __bfloat162float(ha2));
                    __nv_bfloat16 la3 = __float2bfloat16(pa[3] - __bfloat162float(ha3));
                    __nv_bfloat16 lb0 = __float2bfloat16(pb[0] - __bfloat162float(hb0));
                    __nv_bfloat16 lb1 = __float2bfloat16(pb[1] - __bfloat162float(hb1));
                    __nv_bfloat16 lb2 = __float2bfloat16(pb[2] - __bfloat162float(hb2));
                    __nv_bfloat16 lb3 = __float2bfloat16(pb[3] - __bfloat162float(hb3));
                    t = __halves2bfloat162(la0, la1); pl[0] = *(uint32_t*)&t;
                    t = __halves2bfloat162(la2, la3); pl[1] = *(uint32_t*)&t;
                    t = __halves2bfloat162(lb0, lb1); pl[2] = *(uint32_t*)&t;
                    t = __halves2bfloat162(lb2, lb3); pl[3] = *(uint32_t*)&t;
                }
#pragma unroll
                for (int dp = 0; dp < 4; dp++) {
                    uint32_t vh4[4], vl4[4];
                    uint32_t adr = smem_u32(&Vhi[(kv * 16 + vrow) * 72 + dp * 16 + vcol]);
                    ldmatrix_x4_trans(vh4[0], vh4[1], vh4[2], vh4[3], adr);
                    adr = smem_u32(&Vlo[(kv * 16 + vrow) * 72 + dp * 16 + vcol]);
                    ldmatrix_x4_trans(vl4[0], vl4[1], vl4[2], vl4[3], adr);
                    mma_bf16(o[dp * 2],     ph, vh4[0], vh4[1]);
                    mma_bf16(o[dp * 2],     ph, vl4[0], vl4[1]);
                    mma_bf16(o[dp * 2],     pl, vh4[0], vh4[1]);
                    mma_bf16(o[dp * 2 + 1], ph, vh4[2], vh4[3]);
                    mma_bf16(o[dp * 2 + 1], ph, vl4[2], vl4[3]);
                    mma_bf16(o[dp * 2 + 1], pl, vh4[2], vh4[3]);
                }
            }
        }
    }

    // ---- write O / l ----
    const float inv0 = 1.f / lrow[0];
    const float inv1 = 1.f / lrow[1];
    const size_t rg0 = (size_t)(b * TLEN + t0 + wrow0 + (lane >> 2));
#pragma unroll
    for (int nf = 0; nf < 8; nf++) {
        const int cc = h * HD + nf * 8 + (lane & 3) * 2;
        *(float2*)&g_att[rg0 * DM + cc] =
            make_float2(o[nf][0] * inv0, o[nf][1] * inv0);
        *(float2*)&g_att[(rg0 + 8) * DM + cc] =
            make_float2(o[nf][2] * inv1, o[nf][3] * inv1);
    }
}

// ---------------------------------------------------------------------------
// Fused MLP (unchanged).
// ---------------------------------------------------------------------------
__global__ __launch_bounds__(256) void mlp_kernel(const float* __restrict__ W1,
                                                  const float* __restrict__ b1,
                                                  const float* __restrict__ W2,
                                                  const float* __restrict__ b2,
                                                  float* __restrict__ out)
{
    __shared__ float W2s[64 * 65];
    __shared__ float Hs[64 * 65];
    __shared__ float As[64 * 17];
    __shared__ float W1s[16 * 65];

    const int tid = threadIdx.x;
    const int tx  = tid & 15;
    const int ty  = tid >> 4;
    const int r0  = blockIdx.x * 64;

#pragma unroll
    for (int it = 0; it < 4; it++) {
        int lin = (tid + it * 256) * 4;
        int m = lin >> 6, n = lin & 63;
        float4 w = *(const float4*)&W2[m * 64 + n];
        W2s[m * 65 + n + 0] = w.x;
        W2s[m * 65 + n + 1] = w.y;
        W2s[m * 65 + n + 2] = w.z;
        W2s[m * 65 + n + 3] = w.w;
    }

    float acc1[4][4];
#pragma unroll
    for (int i = 0; i < 4; i++)
#pragma unroll
        for (int j = 0; j < 4; j++) acc1[i][j] = 0.f;

    for (int ct = 0; ct < DM; ct += 16) {
        __syncthreads();
        {
            int m = tid >> 2;
            int c = (tid & 3) * 4;
            float4 a = *(const float4*)&g_att[(size_t)(r0 + m) * DM + ct + c];
            As[m * 17 + c + 0] = a.x;
            As[m * 17 + c + 1] = a.y;
            As[m * 17 + c + 2] = a.z;
            As[m * 17 + c + 3] = a.w;
        }
        {
            int c = tid >> 4;
            int n = (tid & 15) * 4;
            float4 w = *(const float4*)&W1[(size_t)(ct + c) * 64 + n];
            W1s[c * 65 + n + 0] = w.x;
            W1s[c * 65 + n + 1] = w.y;
            W1s[c * 65 + n + 2] = w.z;
            W1s[c * 65 + n + 3] = w.w;
        }
        __syncthreads();
#pragma unroll
        for (int c = 0; c < 16; c++) {
            float a[4], w[4];
#pragma unroll
            for (int i = 0; i < 4; i++) a[i] = As[(ty * 4 + i) * 17 + c];
#pragma unroll
            for (int j = 0; j < 4; j++) w[j] = W1s[c * 65 + tx + 16 * j];
#pragma unroll
            for (int i = 0; i < 4; i++)
#pragma unroll
                for (int j = 0; j < 4; j++) acc1[i][j] += a[i] * w[j];
        }
    }

    __syncthreads();
#pragma unroll
    for (int i = 0; i < 4; i++)
#pragma unroll
        for (int j = 0; j < 4; j++)
            Hs[(ty * 4 + i) * 65 + tx + 16 * j] =
                fmaxf(acc1[i][j] + b1[tx + 16 * j], 0.f);
    __syncthreads();

    float acc2[4][4];
#pragma unroll
    for (int i = 0; i < 4; i++)
#pragma unroll
        for (int j = 0; j < 4; j++) acc2[i][j] = 0.f;
#pragma unroll 8
    for (int kv = 0; kv < 64; kv++) {
        float hv[4], w[4];
#pragma unroll
        for (int i = 0; i < 4; i++) hv[i] = Hs[(ty * 4 + i) * 65 + kv];
#pragma unroll
        for (int j = 0; j < 4; j++) w[j] = W2s[kv * 65 + tx + 16 * j];
#pragma unroll
        for (int i = 0; i < 4; i++)
#pragma unroll
            for (int j = 0; j < 4; j++) acc2[i][j] += hv[i] * w[j];
    }

#pragma unroll
    for (int i = 0; i < 4; i++)
#pragma unroll
        for (int j = 0; j < 4; j++)
            out[(size_t)(r0 + ty * 4 + i) * 64 + tx + 16 * j] =
                acc2[i][j] + b2[tx + 16 * j];
}

// ---------------------------------------------------------------------------
extern "C" void kernel_launch(void* const* d_in, const int* in_sizes, int n_in,
                              void* d_out, int out_size)
{
    const float* x  = (const float*)d_in[0];
    const float* Wq = (const float*)d_in[1];
    const float* bq = (const float*)d_in[2];
    const float* Wk = (const float*)d_in[3];
    const float* bk = (const float*)d_in[4];
    const float* Wv = (const float*)d_in[5];
    const float* bv = (const float*)d_in[6];
    const float* W1 = (const float*)d_in[7];
    const float* b1 = (const float*)d_in[8];
    const float* W2 = (const float*)d_in[9];
    const float* b2 = (const float*)d_in[10];
    float* out = (float*)d_out;

    // prep: bf16 hi/lo splits + W transposes
    split_x_kernel<<<(BT * DM / 4 + 255) / 256, 256>>>(x);
    tsplit_w_kernel<<<dim3(3 * DM / 32, DM / 32), 256>>>(Wq, 0, 3 * DM);
    tsplit_w_kernel<<<dim3(3 * DM / 32, DM / 32), 256>>>(Wk, 1, 3 * DM);
    tsplit_w_kernel<<<dim3(DM / 32, DM / 32), 256>>>(Wv, 2, DM);

    // mma.sync bf16x3 projections (emit bf16 hi/lo q/k/v)
    dim3 pg(BT / 128, DM / 128);   // (64, 4)
    proj_mma_kernel<<<pg, 256>>>(bq, 0, 3 * DM, 2);
    proj_mma_kernel<<<pg, 256>>>(bk, 1, 3 * DM, 2);
    proj_mma_kernel<<<pg, 256>>>(bv, 2, DM, 0);

    // attention (mma.sync bf16x3 flash)
    attn_mma_kernel<<<dim3(TLEN / 128, BSZ * NH), 256, ATT_DYNSM>>>();

    mlp_kernel<<<BT / 64, 256>>>(W1, b1, W2, b2, out);
}

// round 5
// speedup vs baseline: 2.5680x; 1.1634x over previous
#include <cuda_runtime.h>
#include <cuda_bf16.h>
#include <cstdint>
#include <math.h>

#define BSZ 4
#define TLEN 2048
#define DM 512
#define NH 8
#define HD 64
#define BT (BSZ*TLEN)

// ---------------------------------------------------------------------------
// device scratch (no runtime allocation allowed)
// ---------------------------------------------------------------------------
__device__ float g_att[BT * DM];

__device__ __nv_bfloat16 g_xhi[BT * DM];
__device__ __nv_bfloat16 g_xlo[BT * DM];
__device__ __nv_bfloat16 g_wqhi[3 * DM * DM];   // transposed: [512][1536]
__device__ __nv_bfloat16 g_wqlo[3 * DM * DM];
__device__ __nv_bfloat16 g_wkhi[3 * DM * DM];
__device__ __nv_bfloat16 g_wklo[3 * DM * DM];
__device__ __nv_bfloat16 g_wvhi[DM * DM];       // transposed: [512][512]
__device__ __nv_bfloat16 g_wvlo[DM * DM];

// projection outputs, bf16 hi/lo (q pre-scaled by 1/sqrt(DK))
__device__ __nv_bfloat16 g_qhi[BT * DM];
__device__ __nv_bfloat16 g_qlo[BT * DM];
__device__ __nv_bfloat16 g_khi[BT * DM];
__device__ __nv_bfloat16 g_klo[BT * DM];
__device__ __nv_bfloat16 g_vhi[BT * DM];
__device__ __nv_bfloat16 g_vlo[BT * DM];

extern __shared__ unsigned char dynsm[];

// ---------------------------------------------------------------------------
__device__ __forceinline__ uint32_t smem_u32(const void* p) {
    uint32_t a;
    asm("{ .reg .u64 t; cvta.to.shared.u64 t, %1; cvt.u32.u64 %0, t; }"
        : "=r"(a) : "l"(p));
    return a;
}

__device__ __forceinline__ void ldmatrix_x4(uint32_t& r0, uint32_t& r1,
                                            uint32_t& r2, uint32_t& r3,
                                            uint32_t addr) {
    asm volatile("ldmatrix.sync.aligned.m8n8.x4.shared.b16 {%0,%1,%2,%3}, [%4];"
                 : "=r"(r0), "=r"(r1), "=r"(r2), "=r"(r3) : "r"(addr));
}

__device__ __forceinline__ void ldmatrix_x4_trans(uint32_t& r0, uint32_t& r1,
                                                  uint32_t& r2, uint32_t& r3,
                                                  uint32_t addr) {
    asm volatile("ldmatrix.sync.aligned.m8n8.x4.trans.shared.b16 {%0,%1,%2,%3}, [%4];"
                 : "=r"(r0), "=r"(r1), "=r"(r2), "=r"(r3) : "r"(addr));
}

__device__ __forceinline__ void mma_bf16(float* d, const uint32_t* a,
                                         uint32_t b0, uint32_t b1) {
    asm volatile(
        "mma.sync.aligned.m16n8k16.row.col.f32.bf16.bf16.f32 "
        "{%0,%1,%2,%3}, {%4,%5,%6,%7}, {%8,%9}, {%0,%1,%2,%3};"
        : "+f"(d[0]), "+f"(d[1]), "+f"(d[2]), "+f"(d[3])
        : "r"(a[0]), "r"(a[1]), "r"(a[2]), "r"(a[3]), "r"(b0), "r"(b1));
}

__device__ __forceinline__ void cp16(uint32_t dst, const void* src, uint32_t bytes) {
    asm volatile("cp.async.cg.shared.global [%0], [%1], 16, %2;"
                 :: "r"(dst), "l"(src), "r"(bytes));
}
#define CP_COMMIT() asm volatile("cp.async.commit_group;" ::: "memory")
#define CP_WAIT1()  asm volatile("cp.async.wait_group 1;" ::: "memory")

// ---------------------------------------------------------------------------
// Prep: split x into bf16 hi/lo
// ---------------------------------------------------------------------------
__global__ __launch_bounds__(256) void split_x_kernel(const float* __restrict__ x)
{
    int i = (blockIdx.x * 256 + threadIdx.x) * 4;
    if (i >= BT * DM) return;
    float4 a = *(const float4*)&x[i];
    float av[4] = {a.x, a.y, a.z, a.w};
#pragma unroll
    for (int j = 0; j < 4; j++) {
        __nv_bfloat16 h = __float2bfloat16(av[j]);
        g_xhi[i + j] = h;
        g_xlo[i + j] = __float2bfloat16(av[j] - __bfloat162float(h));
    }
}

// ---------------------------------------------------------------------------
// Prep: transpose W[K][512] -> Wt[512][K] and split hi/lo
// ---------------------------------------------------------------------------
__global__ __launch_bounds__(256) void tsplit_w_kernel(const float* __restrict__ W,
                                                       int which, int K)
{
    __nv_bfloat16* hiT = (which == 0) ? g_wqhi : (which == 1 ? g_wkhi : g_wvhi);
    __nv_bfloat16* loT = (which == 0) ? g_wqlo : (which == 1 ? g_wklo : g_wvlo);
    __shared__ float t[32][33];
    const int tx = threadIdx.x & 31;
    const int ty = threadIdx.x >> 5;      // 0..7
    const int k0 = blockIdx.x * 32;
    const int n0 = blockIdx.y * 32;
#pragma unroll
    for (int i = 0; i < 4; i++)
        t[ty + 8 * i][tx] = W[(size_t)(k0 + ty + 8 * i) * DM + n0 + tx];
    __syncthreads();
#pragma unroll
    for (int i = 0; i < 4; i++) {
        float a = t[tx][ty + 8 * i];
        __nv_bfloat16 h = __float2bfloat16(a);
        size_t idx = (size_t)(n0 + ty + 8 * i) * K + k0 + tx;
        hiT[idx] = h;
        loT[idx] = __float2bfloat16(a - __bfloat162float(h));
    }
}

// ---------------------------------------------------------------------------
// Fused mma.sync bf16x3 projection GEMM (Q, K, V in one launch).
// Double-buffered cp.async pipeline. 128x128 tile, K-chunk 32, 8 warps.
// Dynamic smem: 2 buffers x {Ahi,Alo,Bhi,Blo}[128][40 bf16] = 81920 B.
// ---------------------------------------------------------------------------
#define PROJ_BUFB 40960          // one buffer (4 arrays x 10240B)
#define PROJ_SMEM (2*PROJ_BUFB)

__global__ __launch_bounds__(256) void proj_mma_kernel(const float* __restrict__ bq,
                                                       const float* __restrict__ bk,
                                                       const float* __restrict__ bv)
{
    const int sub   = blockIdx.y;
    const int which = sub >> 2;
    const int n0    = (sub & 3) * 128;
    const float* bias = (which == 0) ? bq : (which == 1 ? bk : bv);
    const int K     = (which == 2) ? DM : 3 * DM;
    const int shift = (which == 2) ? 0 : 2;
    const float sc  = (which == 0) ? 0.125f : 1.0f;

    const __nv_bfloat16* whiT = (which == 0) ? g_wqhi : (which == 1 ? g_wkhi : g_wvhi);
    const __nv_bfloat16* wloT = (which == 0) ? g_wqlo : (which == 1 ? g_wklo : g_wvlo);
    __nv_bfloat16* ohi = (which == 0) ? g_qhi : (which == 1 ? g_khi : g_vhi);
    __nv_bfloat16* olo = (which == 0) ? g_qlo : (which == 1 ? g_klo : g_vlo);

    const uint32_t sb = smem_u32(dynsm);
    const int tid  = threadIdx.x;
    const int warp = tid >> 5;
    const int lane = tid & 31;
    const int m0 = blockIdx.x * 128;
    const int b  = m0 / TLEN;
    const int tb = m0 % TLEN;

    const int warp_m = (warp & 3) * 32;
    const int warp_n = (warp >> 2) * 64;
    const int a_row = warp_m + (lane & 15);
    const int a_col = (lane >> 4) << 3;
    const int b_row = warp_n + ((lane >> 4) << 3) + (lane & 7);
    const int b_col = ((lane >> 3) & 1) << 3;

    // per-thread cp.async coordinates: 2 iters x (row, 16B seg)
    const int ld_row0 = tid >> 2;              // 0..63   (iter0), +64 iter1
    const int ld_c    = (tid & 3) * 8;         // bf16 col within 32-chunk
    const int ld_sb   = (tid & 3) * 16;        // byte seg within 64B row

    float acc[2][8][4];
#pragma unroll
    for (int mi = 0; mi < 2; mi++)
#pragma unroll
        for (int nf = 0; nf < 8; nf++)
#pragma unroll
            for (int c = 0; c < 4; c++) acc[mi][nf][c] = 0.f;

    const int nchunk = K >> 5;

    // ---- issue loads for chunk ch into buffer bo ----
    auto issue = [&](int ch, uint32_t bo) {
        const int k0 = ch << 5;
        const int f  = k0 >> 9;
        const int c0 = k0 & 511;
#pragma unroll
        for (int it = 0; it < 2; it++) {
            const int row = ld_row0 + it * 64;
            // A (shifted x, zero-fill left pad)
            int ts = tb + row - shift + f;
            uint32_t bytes = (ts >= 0) ? 16u : 0u;
            int tsc = (ts >= 0) ? ts : 0;
            size_t ga = ((size_t)(b * TLEN + tsc)) * DM + c0 + ld_c;
            uint32_t so = row * 80 + ld_sb;
            cp16(bo + so,         &g_xhi[ga], bytes);
            cp16(bo + 10240 + so, &g_xlo[ga], bytes);
            // B (transposed weights [N][K])
            size_t gb = (size_t)(n0 + row) * K + k0 + ld_c;
            cp16(bo + 20480 + so, &whiT[gb], 16u);
            cp16(bo + 30720 + so, &wloT[gb], 16u);
        }
    };

    issue(0, sb);
    CP_COMMIT();

    for (int ch = 0; ch < nchunk; ch++) {
        const uint32_t bo = sb + (ch & 1) * PROJ_BUFB;
        if (ch + 1 < nchunk) issue(ch + 1, sb + ((ch + 1) & 1) * PROJ_BUFB);
        CP_COMMIT();
        CP_WAIT1();
        __syncthreads();

#pragma unroll
        for (int ks = 0; ks < 32; ks += 16) {
            uint32_t ah[2][4], al[2][4];
#pragma unroll
            for (int mi = 0; mi < 2; mi++) {
                uint32_t adr = bo + (a_row + mi * 16) * 80 + (ks + a_col) * 2;
                ldmatrix_x4(ah[mi][0], ah[mi][1], ah[mi][2], ah[mi][3], adr);
                ldmatrix_x4(al[mi][0], al[mi][1], al[mi][2], al[mi][3], adr + 10240);
            }
            uint32_t bh[4][4], bl[4][4];
#pragma unroll
            for (int pi = 0; pi < 4; pi++) {
                uint32_t adr = bo + 20480 + (b_row + pi * 16) * 80 + (ks + b_col) * 2;
                ldmatrix_x4(bh[pi][0], bh[pi][1], bh[pi][2], bh[pi][3], adr);
                ldmatrix_x4(bl[pi][0], bl[pi][1], bl[pi][2], bl[pi][3], adr + 10240);
            }
#pragma unroll
            for (int mi = 0; mi < 2; mi++)
#pragma unroll
                for (int nf = 0; nf < 8; nf++) {
                    const int pi = nf >> 1;
                    const int hh = (nf & 1) << 1;
                    mma_bf16(acc[mi][nf], ah[mi], bh[pi][hh], bh[pi][hh + 1]);
                    mma_bf16(acc[mi][nf], ah[mi], bl[pi][hh], bl[pi][hh + 1]);
                    mma_bf16(acc[mi][nf], al[mi], bh[pi][hh], bh[pi][hh + 1]);
                }
        }
        __syncthreads();   // all reads done before buffer is overwritten
    }

    // epilogue: write bf16 hi/lo (q scaled by 0.125)
#pragma unroll
    for (int mi = 0; mi < 2; mi++) {
        const int r = m0 + warp_m + mi * 16 + (lane >> 2);
#pragma unroll
        for (int nf = 0; nf < 8; nf++) {
            const int cc = n0 + warp_n + nf * 8 + (lane & 3) * 2;
            const float bx = __ldg(&bias[cc]);
            const float by = __ldg(&bias[cc + 1]);
            float v0 = (acc[mi][nf][0] + bx) * sc;
            float v1 = (acc[mi][nf][1] + by) * sc;
            float v2 = (acc[mi][nf][2] + bx) * sc;
            float v3 = (acc[mi][nf][3] + by) * sc;
            __nv_bfloat16 h0 = __float2bfloat16(v0);
            __nv_bfloat16 h1 = __float2bfloat16(v1);
            __nv_bfloat16 h2 = __float2bfloat16(v2);
            __nv_bfloat16 h3 = __float2bfloat16(v3);
            *(__nv_bfloat162*)&ohi[(size_t)r * DM + cc] = __halves2bfloat162(h0, h1);
            *(__nv_bfloat162*)&ohi[(size_t)(r + 8) * DM + cc] = __halves2bfloat162(h2, h3);
            __nv_bfloat16 l0 = __float2bfloat16(v0 - __bfloat162float(h0));
            __nv_bfloat16 l1 = __float2bfloat16(v1 - __bfloat162float(h1));
            __nv_bfloat16 l2 = __float2bfloat16(v2 - __bfloat162float(h2));
            __nv_bfloat16 l3 = __float2bfloat16(v3 - __bfloat162float(h3));
            *(__nv_bfloat162*)&olo[(size_t)r * DM + cc] = __halves2bfloat162(l0, l1);
            *(__nv_bfloat162*)&olo[(size_t)(r + 8) * DM + cc] = __halves2bfloat162(l2, l3);
        }
    }
}

// ---------------------------------------------------------------------------
// Flash attention with mma.sync bf16x3 + cp.async double-buffered K/V tiles.
// Block: 128 q-rows x (b,h). 8 warps x 16 q-rows. K tiles of 64 keys.
// Dynamic smem: 2 buffers x {Khi,Klo,Vhi,Vlo}[64][72 bf16] = 73728 B.
// Q staging (36864 B) aliases buffer 0 (used only before the kv loop).
// ---------------------------------------------------------------------------
#define ATT_BUFB 36864
#define ATT_DYNSM (2*ATT_BUFB)

__global__ __launch_bounds__(256) void attn_mma_kernel()
{
    const uint32_t sb = smem_u32(dynsm);
    const int tid  = threadIdx.x;
    const int warp = tid >> 5;
    const int lane = tid & 31;
    const int qt = (int)gridDim.x - 1 - (int)blockIdx.x;   // heavy tiles first
    const int t0 = qt * 128;
    const int bh = blockIdx.y;
    const int b  = bh >> 3;
    const int h  = bh & 7;
    const int wrow0 = warp * 16;

    // ---- stage Q tile (aliases kv buffers; done before any cp.async) ----
    {
        const size_t base = (size_t)(b * TLEN + t0) * DM + h * HD;
        __nv_bfloat16* Qhi_s = (__nv_bfloat16*)dynsm;            // [128][72]
        __nv_bfloat16* Qlo_s = (__nv_bfloat16*)(dynsm + 18432);
#pragma unroll
        for (int it = 0; it < 4; it++) {
            int idx = tid + it * 256;        // 0..1023
            int row = idx >> 3;
            int seg = (idx & 7) * 8;
            *(uint4*)&Qhi_s[row * 72 + seg] = *(const uint4*)&g_qhi[base + (size_t)row * DM + seg];
            *(uint4*)&Qlo_s[row * 72 + seg] = *(const uint4*)&g_qlo[base + (size_t)row * DM + seg];
        }
    }
    __syncthreads();

    uint32_t qh[4][4], ql[4][4];
    {
        const int a_row = wrow0 + (lane & 15);
        const int a_col = (lane >> 4) << 3;
#pragma unroll
        for (int ks = 0; ks < 4; ks++) {
            uint32_t adr = sb + (a_row * 72 + ks * 16 + a_col) * 2;
            ldmatrix_x4(qh[ks][0], qh[ks][1], qh[ks][2], qh[ks][3], adr);
            ldmatrix_x4(ql[ks][0], ql[ks][1], ql[ks][2], ql[ks][3], adr + 18432);
        }
    }
    __syncthreads();   // all Q reads done before kv prefetch overwrites staging

    float o[8][4];
#pragma unroll
    for (int nf = 0; nf < 8; nf++)
#pragma unroll
        for (int c = 0; c < 4; c++) o[nf][c] = 0.f;
    float mrow[2] = {-1e30f, -1e30f};
    float lrow[2] = {0.f, 0.f};

    const int brow = ((lane >> 4) << 3) + (lane & 7);
    const int bcol = ((lane >> 3) & 1) << 3;
    const int vrow = ((lane >> 3) & 1) * 8 + (lane & 7);
    const int vcol = (lane >> 4) << 3;

    // per-thread cp.async coordinates
    const int kv_row0 = tid >> 3;          // 0..31 (iter0), +32 iter1
    const int kv_seg  = (tid & 7) * 8;     // bf16 col
    const size_t kvbase = (size_t)(b * TLEN) * DM + h * HD;

    auto issue_kv = [&](int kt, uint32_t bo) {
        const size_t base = kvbase + (size_t)(kt * 64) * DM;
#pragma unroll
        for (int it = 0; it < 2; it++) {
            const int row = kv_row0 + it * 32;
            size_t g = base + (size_t)row * DM + kv_seg;
            uint32_t so = (row * 72 + kv_seg) * 2;
            cp16(bo + so,         &g_khi[g], 16u);
            cp16(bo +  9216 + so, &g_klo[g], 16u);
            cp16(bo + 18432 + so, &g_vhi[g], 16u);
            cp16(bo + 27648 + so, &g_vlo[g], 16u);
        }
    };

    const int nkt = 2 * qt + 2;
    issue_kv(0, sb);
    CP_COMMIT();

    for (int kt = 0; kt < nkt; kt++) {
        const int kt0 = kt * 64;
        const uint32_t bo = sb + (kt & 1) * ATT_BUFB;
        if (kt + 1 < nkt) issue_kv(kt + 1, sb + ((kt + 1) & 1) * ATT_BUFB);
        CP_COMMIT();
        CP_WAIT1();
        __syncthreads();

        if (kt0 <= t0 + wrow0 + 15) {    // warp has unmasked keys in this tile
            // ---- S = Q K^T (bf16x3) ----
            float s[8][4];
#pragma unroll
            for (int nf = 0; nf < 8; nf++)
#pragma unroll
                for (int c = 0; c < 4; c++) s[nf][c] = 0.f;
#pragma unroll
            for (int ks = 0; ks < 4; ks++) {
#pragma unroll
                for (int pi = 0; pi < 4; pi++) {
                    uint32_t kh4[4], kl4[4];
                    uint32_t adr = bo + ((pi * 16 + brow) * 72 + ks * 16 + bcol) * 2;
                    ldmatrix_x4(kh4[0], kh4[1], kh4[2], kh4[3], adr);
                    ldmatrix_x4(kl4[0], kl4[1], kl4[2], kl4[3], adr + 9216);
                    mma_bf16(s[pi * 2],     qh[ks], kh4[0], kh4[1]);
                    mma_bf16(s[pi * 2],     qh[ks], kl4[0], kl4[1]);
                    mma_bf16(s[pi * 2],     ql[ks], kh4[0], kh4[1]);
                    mma_bf16(s[pi * 2 + 1], qh[ks], kh4[2], kh4[3]);
                    mma_bf16(s[pi * 2 + 1], qh[ks], kl4[2], kl4[3]);
                    mma_bf16(s[pi * 2 + 1], ql[ks], kh4[2], kh4[3]);
                }
            }

            // ---- causal mask (only near the diagonal) ----
            if (kt0 + 63 > t0 + wrow0) {
                const int r0g = t0 + wrow0 + (lane >> 2);
#pragma unroll
                for (int nf = 0; nf < 8; nf++)
#pragma unroll
                    for (int c = 0; c < 4; c++) {
                        int col = kt0 + nf * 8 + (lane & 3) * 2 + (c & 1);
                        int row = r0g + ((c >> 1) * 8);
                        if (col > row) s[nf][c] = -1e30f;
                    }
            }

            // ---- online softmax ----
#pragma unroll
            for (int half = 0; half < 2; half++) {
                const int c0 = half * 2;
                float mx = -1e30f;
#pragma unroll
                for (int nf = 0; nf < 8; nf++)
                    mx = fmaxf(mx, fmaxf(s[nf][c0], s[nf][c0 + 1]));
                mx = fmaxf(mx, __shfl_xor_sync(0xffffffffu, mx, 1));
                mx = fmaxf(mx, __shfl_xor_sync(0xffffffffu, mx, 2));
                float mnew  = fmaxf(mrow[half], mx);
                float alpha = __expf(mrow[half] - mnew);
                mrow[half] = mnew;
                float sum = 0.f;
#pragma unroll
                for (int nf = 0; nf < 8; nf++) {
                    float p0 = __expf(s[nf][c0] - mnew);
                    float p1 = __expf(s[nf][c0 + 1] - mnew);
                    s[nf][c0] = p0;
                    s[nf][c0 + 1] = p1;
                    sum += p0 + p1;
                }
                sum += __shfl_xor_sync(0xffffffffu, sum, 1);
                sum += __shfl_xor_sync(0xffffffffu, sum, 2);
                lrow[half] = lrow[half] * alpha + sum;
#pragma unroll
                for (int nf = 0; nf < 8; nf++) {
                    o[nf][c0] *= alpha;
                    o[nf][c0 + 1] *= alpha;
                }
            }

            // ---- O += P V (P hi/lo in registers, V via ldmatrix.trans) ----
#pragma unroll
            for (int kv = 0; kv < 4; kv++) {
                uint32_t ph[4], pl[4];
                {
                    const float* pa = s[2 * kv];
                    const float* pb = s[2 * kv + 1];
                    __nv_bfloat16 ha0 = __float2bfloat16(pa[0]);
                    __nv_bfloat16 ha1 = __float2bfloat16(pa[1]);
                    __nv_bfloat16 ha2 = __float2bfloat16(pa[2]);
                    __nv_bfloat16 ha3 = __float2bfloat16(pa[3]);
                    __nv_bfloat16 hb0 = __float2bfloat16(pb[0]);
                    __nv_bfloat16 hb1 = __float2bfloat16(pb[1]);
                    __nv_bfloat16 hb2 = __float2bfloat16(pb[2]);
                    __nv_bfloat16 hb3 = __float2bfloat16(pb[3]);
                    __nv_bfloat162 t;
                    t = __halves2bfloat162(ha0, ha1); ph[0] = *(uint32_t*)&t;
                    t = __halves2bfloat162(ha2, ha3); ph[1] = *(uint32_t*)&t;
                    t = __halves2bfloat162(hb0, hb1); ph[2] = *(uint32_t*)&t;
                    t = __halves2bfloat162(hb2, hb3); ph[3] = *(uint32_t*)&t;
                    __nv_bfloat16 la0 = __float2bfloat16(pa[0] - __bfloat162float(ha0));
                    __nv_bfloat16 la1 = __float2bfloat16(pa[1] - __bfloat162float(ha1));
                    __nv_bfloat16 la2 = __float2bfloat16(pa[2] - __bfloat162float(ha2));
                    __nv_bfloat16 la3 = __float2bfloat16(pa[3] - __bfloat162float(ha3));
                    __nv_bfloat16 lb0 = __float2bfloat16(pb[0] - __bfloat162float(hb0));
                    __nv_bfloat16 lb1 = __float2bfloat16(pb[1] - __bfloat162float(hb1));
                    __nv_bfloat16 lb2 = __float2bfloat16(pb[2] - __bfloat162float(hb2));
                    __nv_bfloat16 lb3 = __float2bfloat16(pb[3] - __bfloat162float(hb3));
                    t = __halves2bfloat162(la0, la1); pl[0] = *(uint32_t*)&t;
                    t = __halves2bfloat162(la2, la3); pl[1] = *(uint32_t*)&t;
                    t = __halves2bfloat162(lb0, lb1); pl[2] = *(uint32_t*)&t;
                    t = __halves2bfloat162(lb2, lb3); pl[3] = *(uint32_t*)&t;
                }
#pragma unroll
                for (int dp = 0; dp < 4; dp++) {
                    uint32_t vh4[4], vl4[4];
                    uint32_t adr = bo + 18432 + ((kv * 16 + vrow) * 72 + dp * 16 + vcol) * 2;
                    ldmatrix_x4_trans(vh4[0], vh4[1], vh4[2], vh4[3], adr);
                    ldmatrix_x4_trans(vl4[0], vl4[1], vl4[2], vl4[3], adr + 9216);
                    mma_bf16(o[dp * 2],     ph, vh4[0], vh4[1]);
                    mma_bf16(o[dp * 2],     ph, vl4[0], vl4[1]);
                    mma_bf16(o[dp * 2],     pl, vh4[0], vh4[1]);
                    mma_bf16(o[dp * 2 + 1], ph, vh4[2], vh4[3]);
                    mma_bf16(o[dp * 2 + 1], ph, vl4[2], vl4[3]);
                    mma_bf16(o[dp * 2 + 1], pl, vh4[2], vh4[3]);
                }
            }
        }
        __syncthreads();   // all reads done before buffer is overwritten
    }

    // ---- write O / l ----
    const float inv0 = 1.f / lrow[0];
    const float inv1 = 1.f / lrow[1];
    const size_t rg0 = (size_t)(b * TLEN + t0 + wrow0 + (lane >> 2));
#pragma unroll
    for (int nf = 0; nf < 8; nf++) {
        const int cc = h * HD + nf * 8 + (lane & 3) * 2;
        *(float2*)&g_att[rg0 * DM + cc] =
            make_float2(o[nf][0] * inv0, o[nf][1] * inv0);
        *(float2*)&g_att[(rg0 + 8) * DM + cc] =
            make_float2(o[nf][2] * inv1, o[nf][3] * inv1);
    }
}

// ---------------------------------------------------------------------------
// Fused MLP (unchanged).
// ---------------------------------------------------------------------------
__global__ __launch_bounds__(256) void mlp_kernel(const float* __restrict__ W1,
                                                  const float* __restrict__ b1,
                                                  const float* __restrict__ W2,
                                                  const float* __restrict__ b2,
                                                  float* __restrict__ out)
{
    __shared__ float W2s[64 * 65];
    __shared__ float Hs[64 * 65];
    __shared__ float As[64 * 17];
    __shared__ float W1s[16 * 65];

    const int tid = threadIdx.x;
    const int tx  = tid & 15;
    const int ty  = tid >> 4;
    const int r0  = blockIdx.x * 64;

#pragma unroll
    for (int it = 0; it < 4; it++) {
        int lin = (tid + it * 256) * 4;
        int m = lin >> 6, n = lin & 63;
        float4 w = *(const float4*)&W2[m * 64 + n];
        W2s[m * 65 + n + 0] = w.x;
        W2s[m * 65 + n + 1] = w.y;
        W2s[m * 65 + n + 2] = w.z;
        W2s[m * 65 + n + 3] = w.w;
    }

    float acc1[4][4];
#pragma unroll
    for (int i = 0; i < 4; i++)
#pragma unroll
        for (int j = 0; j < 4; j++) acc1[i][j] = 0.f;

    for (int ct = 0; ct < DM; ct += 16) {
        __syncthreads();
        {
            int m = tid >> 2;
            int c = (tid & 3) * 4;
            float4 a = *(const float4*)&g_att[(size_t)(r0 + m) * DM + ct + c];
            As[m * 17 + c + 0] = a.x;
            As[m * 17 + c + 1] = a.y;
            As[m * 17 + c + 2] = a.z;
            As[m * 17 + c + 3] = a.w;
        }
        {
            int c = tid >> 4;
            int n = (tid & 15) * 4;
            float4 w = *(const float4*)&W1[(size_t)(ct + c) * 64 + n];
            W1s[c * 65 + n + 0] = w.x;
            W1s[c * 65 + n + 1] = w.y;
            W1s[c * 65 + n + 2] = w.z;
            W1s[c * 65 + n + 3] = w.w;
        }
        __syncthreads();
#pragma unroll
        for (int c = 0; c < 16; c++) {
            float a[4], w[4];
#pragma unroll
            for (int i = 0; i < 4; i++) a[i] = As[(ty * 4 + i) * 17 + c];
#pragma unroll
            for (int j = 0; j < 4; j++) w[j] = W1s[c * 65 + tx + 16 * j];
#pragma unroll
            for (int i = 0; i < 4; i++)
#pragma unroll
                for (int j = 0; j < 4; j++) acc1[i][j] += a[i] * w[j];
        }
    }

    __syncthreads();
#pragma unroll
    for (int i = 0; i < 4; i++)
#pragma unroll
        for (int j = 0; j < 4; j++)
            Hs[(ty * 4 + i) * 65 + tx + 16 * j] =
                fmaxf(acc1[i][j] + b1[tx + 16 * j], 0.f);
    __syncthreads();

    float acc2[4][4];
#pragma unroll
    for (int i = 0; i < 4; i++)
#pragma unroll
        for (int j = 0; j < 4; j++) acc2[i][j] = 0.f;
#pragma unroll 8
    for (int kv = 0; kv < 64; kv++) {
        float hv[4], w[4];
#pragma unroll
        for (int i = 0; i < 4; i++) hv[i] = Hs[(ty * 4 + i) * 65 + kv];
#pragma unroll
        for (int j = 0; j < 4; j++) w[j] = W2s[kv * 65 + tx + 16 * j];
#pragma unroll
        for (int i = 0; i < 4; i++)
#pragma unroll
            for (int j = 0; j < 4; j++) acc2[i][j] += hv[i] * w[j];
    }

#pragma unroll
    for (int i = 0; i < 4; i++)
#pragma unroll
        for (int j = 0; j < 4; j++)
            out[(size_t)(r0 + ty * 4 + i) * 64 + tx + 16 * j] =
                acc2[i][j] + b2[tx + 16 * j];
}

// ---------------------------------------------------------------------------
extern "C" void kernel_launch(void* const* d_in, const int* in_sizes, int n_in,
                              void* d_out, int out_size)
{
    const float* x  = (const float*)d_in[0];
    const float* Wq = (const float*)d_in[1];
    const float* bq = (const float*)d_in[2];
    const float* Wk = (const float*)d_in[3];
    const float* bk = (const float*)d_in[4];
    const float* Wv = (const float*)d_in[5];
    const float* bv = (const float*)d_in[6];
    const float* W1 = (const float*)d_in[7];
    const float* b1 = (const float*)d_in[8];
    const float* W2 = (const float*)d_in[9];
    const float* b2 = (const float*)d_in[10];
    float* out = (float*)d_out;

    // prep: bf16 hi/lo splits + W transposes
    split_x_kernel<<<(BT * DM / 4 + 255) / 256, 256>>>(x);
    tsplit_w_kernel<<<dim3(3 * DM / 32, DM / 32), 256>>>(Wq, 0, 3 * DM);
    tsplit_w_kernel<<<dim3(3 * DM / 32, DM / 32), 256>>>(Wk, 1, 3 * DM);
    tsplit_w_kernel<<<dim3(DM / 32, DM / 32), 256>>>(Wv, 2, DM);

    // fused mma.sync bf16x3 projections (Q, K, V in one launch)
    cudaFuncSetAttribute(proj_mma_kernel,
                         cudaFuncAttributeMaxDynamicSharedMemorySize, PROJ_SMEM);
    proj_mma_kernel<<<dim3(BT / 128, 12), 256, PROJ_SMEM>>>(bq, bk, bv);

    // attention (mma.sync bf16x3 flash, double-buffered K/V)
    cudaFuncSetAttribute(attn_mma_kernel,
                         cudaFuncAttributeMaxDynamicSharedMemorySize, ATT_DYNSM);
    attn_mma_kernel<<<dim3(TLEN / 128, BSZ * NH), 256, ATT_DYNSM>>>();

    mlp_kernel<<<BT / 64, 256>>>(W1, b1, W2, b2, out);
}